// round 6
// baseline (speedup 1.0000x reference)
#include <cuda_runtime.h>

// Shapes (compile-time constants from the reference)
constexpr int B  = 2;
constexpr int L  = 24;
constexpr int R  = 8;
constexpr int C  = 32;
constexpr int H  = 48;
constexpr int WF = 49;

constexpr int RCW  = R * C * WF;        // 12,544   (A elements per (b,l))
constexpr int HW   = H * WF;            // 2,352
constexpr int RCHW = R * C * H * WF;    // 602,112  (u elements per (b,l))
constexpr int NA   = B * L * RCW;       // 602,112  (total A elements)
constexpr int NU   = B * L * RCHW;      // 28,901,376 (u elements per array)

constexpr int ELEMS_PER_BLOCK = 1024;   // 256 threads x 4 elements
constexpr int A_SPAN = 2 * WF;          // 98: block spans <= 2 rc values

// Precomputed transition coefficients A = decay * (cos, sin), interleaved
// float2. 4.8 MB, written by kernel 1, L2-resident for kernel 2's staging.
__device__ float2 g_A[NA];

// ---------------------------------------------------------------------------
// Kernel 1: A[b,l,r,c,w] = exp(-nu*dt) * (cos(th*dt), sin(th*dt))
// Fast-math intrinsics: args are small (|nu*dt| <= 1.1), rel-err headroom is
// 4 decades (1e-7 measured vs 1e-3 threshold). Cuts ~6us of software
// transcendental sequences to ~0.5us of MUFU.
// ---------------------------------------------------------------------------
__global__ void compute_A_kernel(const float* __restrict__ nu_rate,
                                 const float* __restrict__ theta_rate,
                                 const float* __restrict__ dt_seq) {
    int i = blockIdx.x * blockDim.x + threadIdx.x;
    if (i >= NA) return;
    int bl = i / RCW;                 // 0..B*L-1
    float dt = dt_seq[bl];
    float decay = __expf(-nu_rate[i] * dt);
    float s, c;
    __sincosf(theta_rate[i] * dt, &s, &c);
    g_A[i] = make_float2(decay * c, decay * s);
}

// ---------------------------------------------------------------------------
// Kernel 2: sequential complex recurrence over L in registers.
// One thread owns 4 consecutive flat channels (float4-vectorized u/out).
// h_l = A_l * h_{l-1} + u_l  (complex), h_{-1} = 0.
//
// A is staged in shared memory: a block's 1024 contiguous elements span at
// most 2 rc values, so per l the needed A values are 98 CONSECUTIVE float2
// starting at (bL+l)*RCW + rc0*WF. 24 x 98 x 8B = 18.8 KB smem, loaded once,
// replacing 4 scalar L2 LDGs per thread-iteration with LDS.
// ---------------------------------------------------------------------------
__global__ void __launch_bounds__(256, 4)
scan_kernel(const float4* __restrict__ ur,
            const float4* __restrict__ ui,
            float4* __restrict__ out) {
    __shared__ float2 sA[L][A_SPAN];          // 18,816 B

    const int base  = blockIdx.x * ELEMS_PER_BLOCK;  // first flat element
    const int b     = base / RCHW;
    const int sflat = base - b * RCHW;               // block start in batch
    const int rc0   = sflat / HW;                    // first rc in block
    const int bL    = b * L;

    // Cooperative stage of A: 24 chunks of 98 consecutive float2.
    // Clamp guards the rc0+1 overrun at the very last (b,l,rc) chunk; those
    // values are never read (rc0==R*C-1 implies the block stays in rc0).
    for (int i = threadIdx.x; i < L * A_SPAN; i += 256) {
        int l = i / A_SPAN;
        int j = i - l * A_SPAN;
        int gidx = (bL + l) * RCW + rc0 * WF + j;
        if (gidx > NA - 1) gidx = NA - 1;
        (&sA[0][0])[i] = g_A[gidx];
    }
    __syncthreads();

    const int flat = sflat + threadIdx.x * 4;        // first element in batch
    // Per-lane smem A indices (constant across l): j = (e/HW - rc0)*WF + e%WF
    const int j0 = ((flat    ) / HW - rc0) * WF + (flat    ) % WF;
    const int j1 = ((flat + 1) / HW - rc0) * WF + (flat + 1) % WF;
    const int j2 = ((flat + 2) / HW - rc0) * WF + (flat + 2) % WF;
    const int j3 = ((flat + 3) / HW - rc0) * WF + (flat + 3) % WF;

    float hr0 = 0.f, hi0 = 0.f, hr1 = 0.f, hi1 = 0.f;
    float hr2 = 0.f, hi2 = 0.f, hr3 = 0.f, hi3 = 0.f;

    const int flat4 = flat >> 2;

    // Explicit 1-deep prefetch rotation on the streaming u loads.
    int uoff4 = bL * (RCHW >> 2) + flat4;
    float4 vr = __ldcs(&ur[uoff4]);
    float4 vi = __ldcs(&ui[uoff4]);

    #pragma unroll
    for (int l = 0; l < L; ++l) {
        float4 nvr = make_float4(0.f, 0.f, 0.f, 0.f);
        float4 nvi = make_float4(0.f, 0.f, 0.f, 0.f);
        const int noff4 = uoff4 + (RCHW >> 2);
        if (l < L - 1) {
            nvr = __ldcs(&ur[noff4]);
            nvi = __ldcs(&ui[noff4]);
        }

        const float2 A0 = sA[l][j0];
        const float2 A1 = sA[l][j1];
        const float2 A2 = sA[l][j2];
        const float2 A3 = sA[l][j3];

        float nr, ni;
        nr = A0.x * hr0 - A0.y * hi0 + vr.x;
        ni = A0.x * hi0 + A0.y * hr0 + vi.x;
        hr0 = nr; hi0 = ni;

        nr = A1.x * hr1 - A1.y * hi1 + vr.y;
        ni = A1.x * hi1 + A1.y * hr1 + vi.y;
        hr1 = nr; hi1 = ni;

        nr = A2.x * hr2 - A2.y * hi2 + vr.z;
        ni = A2.x * hi2 + A2.y * hr2 + vi.z;
        hr2 = nr; hi2 = ni;

        nr = A3.x * hr3 - A3.y * hi3 + vr.w;
        ni = A3.x * hi3 + A3.y * hr3 + vi.w;
        hr3 = nr; hi3 = ni;

        __stcs(&out[uoff4],             make_float4(hr0, hr1, hr2, hr3)); // real
        __stcs(&out[(NU >> 2) + uoff4], make_float4(hi0, hi1, hi2, hi3)); // imag

        uoff4 = noff4;
        vr = nvr; vi = nvi;
    }
}

// ---------------------------------------------------------------------------
// kernel_launch: two launches, graph-capturable, no allocations.
// Inputs (metadata order): nu_rate, theta_rate, dt_seq, u_real, u_imag.
// Output: float32, shape (2, B, L, R, C, H, Wf) = 57,802,752 elements.
// ---------------------------------------------------------------------------
extern "C" void kernel_launch(void* const* d_in, const int* in_sizes, int n_in,
                              void* d_out, int out_size) {
    const float*  nu = (const float*)d_in[0];
    const float*  th = (const float*)d_in[1];
    const float*  dt = (const float*)d_in[2];
    const float4* ur = (const float4*)d_in[3];
    const float4* ui = (const float4*)d_in[4];
    float4* out = (float4*)d_out;

    compute_A_kernel<<<(NA + 255) / 256, 256>>>(nu, th, dt);

    constexpr int nblocks = (B * RCHW) / ELEMS_PER_BLOCK;   // 1176
    scan_kernel<<<nblocks, 256>>>(ur, ui, out);
}

// round 8
// speedup vs baseline: 1.0034x; 1.0034x over previous
#include <cuda_runtime.h>

// Shapes (compile-time constants from the reference)
constexpr int B  = 2;
constexpr int L  = 24;
constexpr int R  = 8;
constexpr int C  = 32;
constexpr int H  = 48;
constexpr int WF = 49;

constexpr int RCW  = R * C * WF;        // 12,544   (A elements per (b,l))
constexpr int HW   = H * WF;            // 2,352
constexpr int RCHW = R * C * H * WF;    // 602,112  (u elements per (b,l))
constexpr int NA   = B * L * RCW;       // 602,112  (total A elements)
constexpr int NU   = B * L * RCHW;      // 28,901,376 (u elements per array)

constexpr int ELEMS_PER_BLOCK = 1024;   // 256 threads x 4 elements
constexpr int A_SPAN = 2 * WF;          // 98: block spans <= 2 rc values
constexpr int SROW   = 104;             // 98 + skew room (max phys = 97+6=103)

// ---------------------------------------------------------------------------
// Single fused kernel.
//
// Prologue: each block computes its own A = exp(-nu*dt)*(cos,sin) slice
// (24 l x 98 consecutive (rc,w) entries) straight from nu/theta/dt into
// shared memory. Fast-math intrinsics (rel-err headroom is 4 decades).
// This removes the separate compute_A kernel AND all in-loop A traffic.
//
// Smem layout is SKEWED: phys = j + (j>>4). The consumer reads with lane
// stride 4 in j; the skew makes phys mod 16 a permutation per 16-lane phase
// -> conflict-free LDS.64 (round 6's regression was 4-way conflicts here).
//
// Main loop: round-3 body verbatim (it measured best): float4 u loads
// (__ldcs, read-once), complex FMA update in registers, float4 __stcs out.
// No manual prefetch rotation — ptxas schedules the unrolled loop better.
// ---------------------------------------------------------------------------
__global__ void __launch_bounds__(256, 4)
fused_scan_kernel(const float*  __restrict__ nu_rate,
                  const float*  __restrict__ theta_rate,
                  const float*  __restrict__ dt_seq,
                  const float4* __restrict__ ur,
                  const float4* __restrict__ ui,
                  float4*       __restrict__ out) {
    __shared__ float2 sA[L * SROW];          // 19,968 B

    const int base  = blockIdx.x * ELEMS_PER_BLOCK;  // first flat element
    const int b     = base / RCHW;
    const int sflat = base - b * RCHW;               // block start in batch
    const int rc0   = sflat / HW;                    // first rc in block
    const int bL    = b * L;

    // ---- Prologue: compute A slice into skewed smem ----
    // Clamp guards the rc0+1 overrun on the last chunks; clamped entries are
    // never read (a block never spans past the last rc of its batch).
    for (int i = threadIdx.x; i < L * A_SPAN; i += 256) {
        int l = i / A_SPAN;
        int j = i - l * A_SPAN;
        int g = (bL + l) * RCW + rc0 * WF + j;
        if (g > NA - 1) g = NA - 1;
        float dt    = dt_seq[bL + l];
        float decay = __expf(-nu_rate[g] * dt);
        float s, c;
        __sincosf(theta_rate[g] * dt, &s, &c);
        sA[l * SROW + j + (j >> 4)] = make_float2(decay * c, decay * s);
    }
    __syncthreads();

    // ---- Per-lane skewed smem indices (constant across l) ----
    const int flat = sflat + threadIdx.x * 4;        // first element in batch
    int p0, p1, p2, p3;
    {
        int j0 = ((flat    ) / HW - rc0) * WF + (flat    ) % WF;
        int j1 = ((flat + 1) / HW - rc0) * WF + (flat + 1) % WF;
        int j2 = ((flat + 2) / HW - rc0) * WF + (flat + 2) % WF;
        int j3 = ((flat + 3) / HW - rc0) * WF + (flat + 3) % WF;
        p0 = j0 + (j0 >> 4);
        p1 = j1 + (j1 >> 4);
        p2 = j2 + (j2 >> 4);
        p3 = j3 + (j3 >> 4);
    }

    float hr0 = 0.f, hi0 = 0.f, hr1 = 0.f, hi1 = 0.f;
    float hr2 = 0.f, hi2 = 0.f, hr3 = 0.f, hi3 = 0.f;

    const int flat4 = flat >> 2;

    #pragma unroll
    for (int l = 0; l < L; ++l) {
        const int uoff4 = (bL + l) * (RCHW >> 2) + flat4;  // float4 index
        const float4 vr = __ldcs(&ur[uoff4]);   // read-once: evict-first
        const float4 vi = __ldcs(&ui[uoff4]);

        const float2 A0 = sA[l * SROW + p0];
        const float2 A1 = sA[l * SROW + p1];
        const float2 A2 = sA[l * SROW + p2];
        const float2 A3 = sA[l * SROW + p3];

        float nr, ni;
        nr = A0.x * hr0 - A0.y * hi0 + vr.x;
        ni = A0.x * hi0 + A0.y * hr0 + vi.x;
        hr0 = nr; hi0 = ni;

        nr = A1.x * hr1 - A1.y * hi1 + vr.y;
        ni = A1.x * hi1 + A1.y * hr1 + vi.y;
        hr1 = nr; hi1 = ni;

        nr = A2.x * hr2 - A2.y * hi2 + vr.z;
        ni = A2.x * hi2 + A2.y * hr2 + vi.z;
        hr2 = nr; hi2 = ni;

        nr = A3.x * hr3 - A3.y * hi3 + vr.w;
        ni = A3.x * hi3 + A3.y * hr3 + vi.w;
        hr3 = nr; hi3 = ni;

        __stcs(&out[uoff4],             make_float4(hr0, hr1, hr2, hr3)); // real
        __stcs(&out[(NU >> 2) + uoff4], make_float4(hi0, hi1, hi2, hi3)); // imag
    }
}

// ---------------------------------------------------------------------------
// kernel_launch: ONE launch, graph-capturable, no allocations.
// Inputs (metadata order): nu_rate, theta_rate, dt_seq, u_real, u_imag.
// Output: float32, shape (2, B, L, R, C, H, Wf) = 57,802,752 elements.
// ---------------------------------------------------------------------------
extern "C" void kernel_launch(void* const* d_in, const int* in_sizes, int n_in,
                              void* d_out, int out_size) {
    const float*  nu = (const float*)d_in[0];
    const float*  th = (const float*)d_in[1];
    const float*  dt = (const float*)d_in[2];
    const float4* ur = (const float4*)d_in[3];
    const float4* ui = (const float4*)d_in[4];
    float4* out = (float4*)d_out;

    constexpr int nblocks = (B * RCHW) / ELEMS_PER_BLOCK;   // 1176
    fused_scan_kernel<<<nblocks, 256>>>(nu, th, dt, ur, ui, out);
}

// round 9
// speedup vs baseline: 1.0524x; 1.0488x over previous
#include <cuda_runtime.h>

// Shapes (compile-time constants from the reference)
constexpr int B  = 2;
constexpr int L  = 24;
constexpr int R  = 8;
constexpr int C  = 32;
constexpr int H  = 48;
constexpr int WF = 49;

constexpr int RCW  = R * C * WF;        // 12,544   (A elements per (b,l))
constexpr int HW   = H * WF;            // 2,352
constexpr int RCHW = R * C * H * WF;    // 602,112  (u elements per (b,l))
constexpr int NA   = B * L * RCW;       // 602,112  (total A elements)
constexpr int NU   = B * L * RCHW;      // 28,901,376 (u elements per array)

// Precomputed transition coefficients A = decay * (cos, sin), interleaved
// float2. 4.8 MB -> L2-resident during the scan kernel. The in-loop A LDGs
// are deliberately kept as GLOBAL loads: measured R3 vs R6/R8 shows they add
// useful MLP (DRAM 71.1% with them, 64-66% with smem staging instead).
__device__ float2 g_A[NA];

// ---------------------------------------------------------------------------
// Kernel 1: A[b,l,r,c,w] = exp(-nu*dt) * (cos(th*dt), sin(th*dt))
// Fast-math intrinsics: args are small (|nu*dt| <= 1.1); measured rel_err
// with them is 2.5e-7 vs the 1e-3 threshold. ~2us total.
// ---------------------------------------------------------------------------
__global__ void compute_A_kernel(const float* __restrict__ nu_rate,
                                 const float* __restrict__ theta_rate,
                                 const float* __restrict__ dt_seq) {
    int i = blockIdx.x * blockDim.x + threadIdx.x;
    if (i >= NA) return;
    int bl = i / RCW;                 // 0..B*L-1
    float dt = dt_seq[bl];
    float decay = __expf(-nu_rate[i] * dt);
    float s, c;
    __sincosf(theta_rate[i] * dt, &s, &c);
    g_A[i] = make_float2(decay * c, decay * s);
}

// ---------------------------------------------------------------------------
// Kernel 2: sequential complex recurrence over L in registers.
// One thread owns 4 consecutive flat channels (float4-vectorized u/out).
// h_l = A_l * h_{l-1} + u_l  (complex), h_{-1} = 0.
// This is the round-3 kernel verbatim (best measured: 71.4us, DRAM 71.1%).
// ---------------------------------------------------------------------------
__global__ void __launch_bounds__(256, 4)
scan_kernel(const float4* __restrict__ ur,
            const float4* __restrict__ ui,
            float4* __restrict__ out) {
    int t = blockIdx.x * blockDim.x + threadIdx.x;   // 0 .. 301,055
    int base = t * 4;                                 // global element index
    int b    = base / RCHW;                           // batch
    int flat = base - b * RCHW;                       // channel within batch

    // A index per lane: a_flat = (e/HW)*WF + (e%WF); constant across l
    // (stride RCW per step), so compute once.
    int aidx0, aidx1, aidx2, aidx3;
    {
        int e0 = flat;
        aidx0 = (e0 / HW) * WF + (e0 % WF);
        int e1 = flat + 1;
        aidx1 = (e1 / HW) * WF + (e1 % WF);
        int e2 = flat + 2;
        aidx2 = (e2 / HW) * WF + (e2 % WF);
        int e3 = flat + 3;
        aidx3 = (e3 / HW) * WF + (e3 % WF);
    }

    float hr0 = 0.f, hi0 = 0.f, hr1 = 0.f, hi1 = 0.f;
    float hr2 = 0.f, hi2 = 0.f, hr3 = 0.f, hi3 = 0.f;

    const int bL = b * L;
    const int flat4 = flat >> 2;

    #pragma unroll
    for (int l = 0; l < L; ++l) {
        const int uoff4 = (bL + l) * (RCHW >> 2) + flat4;  // float4 index
        const float4 vr = __ldcs(&ur[uoff4]);   // read-once: evict-first
        const float4 vi = __ldcs(&ui[uoff4]);

        const int aoff = (bL + l) * RCW;
        const float2 A0 = g_A[aoff + aidx0];
        const float2 A1 = g_A[aoff + aidx1];
        const float2 A2 = g_A[aoff + aidx2];
        const float2 A3 = g_A[aoff + aidx3];

        float nr, ni;
        nr = A0.x * hr0 - A0.y * hi0 + vr.x;
        ni = A0.x * hi0 + A0.y * hr0 + vi.x;
        hr0 = nr; hi0 = ni;

        nr = A1.x * hr1 - A1.y * hi1 + vr.y;
        ni = A1.x * hi1 + A1.y * hr1 + vi.y;
        hr1 = nr; hi1 = ni;

        nr = A2.x * hr2 - A2.y * hi2 + vr.z;
        ni = A2.x * hi2 + A2.y * hr2 + vi.z;
        hr2 = nr; hi2 = ni;

        nr = A3.x * hr3 - A3.y * hi3 + vr.w;
        ni = A3.x * hi3 + A3.y * hr3 + vi.w;
        hr3 = nr; hi3 = ni;

        __stcs(&out[uoff4],             make_float4(hr0, hr1, hr2, hr3)); // real half
        __stcs(&out[(NU >> 2) + uoff4], make_float4(hi0, hi1, hi2, hi3)); // imag half
    }
}

// ---------------------------------------------------------------------------
// kernel_launch: two launches, graph-capturable, no allocations.
// Inputs (metadata order): nu_rate, theta_rate, dt_seq, u_real, u_imag.
// Output: float32, shape (2, B, L, R, C, H, Wf) = 57,802,752 elements.
// ---------------------------------------------------------------------------
extern "C" void kernel_launch(void* const* d_in, const int* in_sizes, int n_in,
                              void* d_out, int out_size) {
    const float*  nu = (const float*)d_in[0];
    const float*  th = (const float*)d_in[1];
    const float*  dt = (const float*)d_in[2];
    const float4* ur = (const float4*)d_in[3];
    const float4* ui = (const float4*)d_in[4];
    float4* out = (float4*)d_out;

    compute_A_kernel<<<(NA + 255) / 256, 256>>>(nu, th, dt);

    constexpr int nthreads = (B * RCHW) / 4;   // 301,056
    scan_kernel<<<nthreads / 256, 256>>>(ur, ui, out);
}